// round 10
// baseline (speedup 1.0000x reference)
#include <cuda_runtime.h>
#include <cuda_bf16.h>
#include <math.h>
#include <stdint.h>

#define BATCH 2
#define SEQ 2048
#define DM 1024
#define NH 16
#define DK 64
#define MROWS (BATCH * SEQ)          // 4096
#define BH (BATCH * NH)              // 32

// Scratch (allocation-free rule: __device__ globals)
__device__ float g_q[BH * SEQ * DK];     // [b,h,s,dk]
__device__ float g_k[BH * SEQ * DK];
__device__ float g_v[BH * SEQ * DK];
__device__ float g_ctx[MROWS * DM];      // [b*s, h*dk]

// ---------------------------------------------------------------------------
// bf16 split-precision mma helpers (3xBF16 ~= fp32 accuracy, err ~1e-5)
// ---------------------------------------------------------------------------
__device__ __forceinline__ void mma_bf16(float c[4], const uint32_t a[4], const uint32_t b[2]) {
    asm volatile(
        "mma.sync.aligned.m16n8k16.row.col.f32.bf16.bf16.f32 "
        "{%0,%1,%2,%3}, {%4,%5,%6,%7}, {%8,%9}, {%0,%1,%2,%3};\n"
        : "+f"(c[0]), "+f"(c[1]), "+f"(c[2]), "+f"(c[3])
        : "r"(a[0]), "r"(a[1]), "r"(a[2]), "r"(a[3]), "r"(b[0]), "r"(b[1]));
}

__device__ __forceinline__ void split_pack(float f0, float f1, uint32_t& hi, uint32_t& lo) {
    __nv_bfloat16 h0 = __float2bfloat16_rn(f0);
    __nv_bfloat16 h1 = __float2bfloat16_rn(f1);
    float r0 = f0 - __bfloat162float(h0);
    float r1 = f1 - __bfloat162float(h1);
    __nv_bfloat162 H; H.x = h0; H.y = h1;
    __nv_bfloat162 L; L.x = __float2bfloat16_rn(r0); L.y = __float2bfloat16_rn(r1);
    hi = *reinterpret_cast<uint32_t*>(&H);
    lo = *reinterpret_cast<uint32_t*>(&L);
}

#define SP 136   // padded stride (uint2) over m/n dim

// ---------------------------------------------------------------------------
// Unified NT tensor-core GEMM: C[M,N] = A[M,K] @ B[N,K]^T
// Block 128x128, 8 warps (2x4), warp tile 64x32, BK=16, double-buffered smem.
// hi/lo interleaved as uint2 -> LDS.64 fragment loads (half the LDS count).
// MODE 0: proj   (A=x, B=wq/wk/wv via z, K=1024, head-major scatter epilogue)
// MODE 1: scores (A=g_q[z], B=g_k[z], K=64, scale+mask epilogue -> attn)
// MODE 2: outproj(A=g_ctx, B=wo, K=1024, plain epilogue)
// ---------------------------------------------------------------------------
template<int MODE>
__global__ void __launch_bounds__(256, 2)
gemm_nt_kernel(const float* __restrict__ Ain, const float* __restrict__ B0,
               const float* __restrict__ B1,  const float* __restrict__ B2,
               const int* __restrict__ mask,  float* __restrict__ outp)
{
    constexpr int KD    = (MODE == 1) ? DK : DM;
    constexpr int NITER = KD / 16;

    __shared__ uint2 AsP[2][8][SP];
    __shared__ uint2 BsP[2][8][SP];

    const int t  = threadIdx.x;
    const int z  = blockIdx.z;
    const int m0 = blockIdx.y * 128;
    const int n0 = blockIdx.x * 128;

    const float* A;
    const float* B;
    if (MODE == 0)      { A = Ain; B = (z == 0) ? B0 : (z == 1) ? B1 : B2; }
    else if (MODE == 1) { A = g_q + (size_t)z * SEQ * DK; B = g_k + (size_t)z * SEQ * DK; }
    else                { A = g_ctx; B = B0; }

    const int lrow = t >> 1;
    const int sel  = t & 1;
    const int kc   = sel * 8;
    const int k2b  = kc >> 1;                  // 0 or 4
    const float* pA = A + (size_t)(m0 + lrow) * KD + kc;
    const float* pB = B + (size_t)(n0 + lrow) * KD + kc;

    float4 ra0 = *(const float4*)(pA);
    float4 ra1 = *(const float4*)(pA + 4);
    float4 rb0 = *(const float4*)(pB);
    float4 rb1 = *(const float4*)(pB + 4);

    {
        uint32_t h[4], l[4];
        split_pack(ra0.x, ra0.y, h[0], l[0]);
        split_pack(ra0.z, ra0.w, h[1], l[1]);
        split_pack(ra1.x, ra1.y, h[2], l[2]);
        split_pack(ra1.z, ra1.w, h[3], l[3]);
        #pragma unroll
        for (int i = 0; i < 4; i++) {
            int j = i ^ sel;
            AsP[0][k2b + j][lrow] = make_uint2(h[j], l[j]);
        }
        split_pack(rb0.x, rb0.y, h[0], l[0]);
        split_pack(rb0.z, rb0.w, h[1], l[1]);
        split_pack(rb1.x, rb1.y, h[2], l[2]);
        split_pack(rb1.z, rb1.w, h[3], l[3]);
        #pragma unroll
        for (int i = 0; i < 4; i++) {
            int j = i ^ sel;
            BsP[0][k2b + j][lrow] = make_uint2(h[j], l[j]);
        }
    }
    __syncthreads();

    const int warp = t >> 5, lane = t & 31;
    const int wm = (warp >> 2) * 64;
    const int wn = (warp & 3) * 32;
    const int qrow = lane >> 2, qk = lane & 3;

    float c[4][4][4] = {};

    for (int it = 0; it < NITER; ++it) {
        const int buf = it & 1;
        if (it + 1 < NITER) {
            const float* qa = pA + (it + 1) * 16;
            const float* qb = pB + (it + 1) * 16;
            ra0 = *(const float4*)(qa); ra1 = *(const float4*)(qa + 4);
            rb0 = *(const float4*)(qb); rb1 = *(const float4*)(qb + 4);
        }

        uint32_t aH[4][4], aL[4][4], bH[4][2], bL[4][2];
        #pragma unroll
        for (int mt = 0; mt < 4; mt++) {
            int m = wm + mt * 16 + qrow;
            uint2 p0 = AsP[buf][qk][m];
            uint2 p1 = AsP[buf][qk][m + 8];
            uint2 p2 = AsP[buf][qk + 4][m];
            uint2 p3 = AsP[buf][qk + 4][m + 8];
            aH[mt][0] = p0.x; aH[mt][1] = p1.x; aH[mt][2] = p2.x; aH[mt][3] = p3.x;
            aL[mt][0] = p0.y; aL[mt][1] = p1.y; aL[mt][2] = p2.y; aL[mt][3] = p3.y;
        }
        #pragma unroll
        for (int nt = 0; nt < 4; nt++) {
            int n = wn + nt * 8 + qrow;
            uint2 q0 = BsP[buf][qk][n];
            uint2 q1 = BsP[buf][qk + 4][n];
            bH[nt][0] = q0.x; bH[nt][1] = q1.x;
            bL[nt][0] = q0.y; bL[nt][1] = q1.y;
        }
        #pragma unroll
        for (int mt = 0; mt < 4; mt++)
            #pragma unroll
            for (int nt = 0; nt < 4; nt++) {
                mma_bf16(c[mt][nt], aH[mt], bH[nt]);
                mma_bf16(c[mt][nt], aH[mt], bL[nt]);
                mma_bf16(c[mt][nt], aL[mt], bH[nt]);
            }

        if (it + 1 < NITER) {
            const int nb = buf ^ 1;
            uint32_t h[4], l[4];
            split_pack(ra0.x, ra0.y, h[0], l[0]);
            split_pack(ra0.z, ra0.w, h[1], l[1]);
            split_pack(ra1.x, ra1.y, h[2], l[2]);
            split_pack(ra1.z, ra1.w, h[3], l[3]);
            #pragma unroll
            for (int i = 0; i < 4; i++) {
                int j = i ^ sel;
                AsP[nb][k2b + j][lrow] = make_uint2(h[j], l[j]);
            }
            split_pack(rb0.x, rb0.y, h[0], l[0]);
            split_pack(rb0.z, rb0.w, h[1], l[1]);
            split_pack(rb1.x, rb1.y, h[2], l[2]);
            split_pack(rb1.z, rb1.w, h[3], l[3]);
            #pragma unroll
            for (int i = 0; i < 4; i++) {
                int j = i ^ sel;
                BsP[nb][k2b + j][lrow] = make_uint2(h[j], l[j]);
            }
        }
        __syncthreads();
    }

    #pragma unroll
    for (int mt = 0; mt < 4; mt++) {
        #pragma unroll
        for (int nt = 0; nt < 4; nt++) {
            int mg = m0 + wm + mt * 16 + qrow;
            int ng = n0 + wn + nt * 8 + qk * 2;
            #pragma unroll
            for (int half = 0; half < 2; half++) {
                int m = mg + half * 8;
                float v0 = c[mt][nt][half * 2 + 0];
                float v1 = c[mt][nt][half * 2 + 1];
                if (MODE == 0) {
                    float* outg = (z == 0) ? g_q : (z == 1) ? g_k : g_v;
                    int b = m >> 11, s = m & (SEQ - 1);
                    int h = ng >> 6, d = ng & 63;
                    float2 w = {v0, v1};
                    *(float2*)(outg + ((size_t)(b * NH + h) * SEQ + s) * DK + d) = w;
                } else if (MODE == 1) {
                    int bb = z >> 4;
                    int mk0 = mask[bb * SEQ + ng];
                    int mk1 = mask[bb * SEQ + ng + 1];
                    float2 w;
                    w.x = mk0 ? -1e9f : v0 * 0.125f;
                    w.y = mk1 ? -1e9f : v1 * 0.125f;
                    *(float2*)(outp + ((size_t)z * SEQ + m) * SEQ + ng) = w;
                } else {
                    float2 w = {v0, v1};
                    *(float2*)(outp + (size_t)m * DM + ng) = w;
                }
            }
        }
    }
}

// ---------------------------------------------------------------------------
// ctx = attn @ V  (NN).  Per head: M=2048, N=64, K=2048.
// Block 128x64, 8 warps (4x2), warp tile 32x32, BK=16, double-buffered,
// uint2-merged smem.
// ---------------------------------------------------------------------------
__global__ void __launch_bounds__(256, 2)
ctx_kernel(const float* __restrict__ attn)
{
    __shared__ uint2 AsP[2][8][SP];
    __shared__ uint2 BsP[2][8][72];

    const int t  = threadIdx.x;
    const int z  = blockIdx.z;                 // bh
    const int m0 = blockIdx.y * 128;
    const float* A = attn + (size_t)z * SEQ * SEQ;
    const float* V = g_v  + (size_t)z * SEQ * DK;

    const int lrow = t >> 1;
    const int sel  = t & 1;
    const int kc   = sel * 8;
    const int k2b  = kc >> 1;
    const float* pA = A + (size_t)(m0 + lrow) * SEQ + kc;

    float4 ra0 = *(const float4*)(pA);
    float4 ra1 = *(const float4*)(pA + 4);
    float vb[2][2];
    #pragma unroll
    for (int i = 0; i < 2; i++) {
        int p = t + 256 * i;
        int pk2 = p >> 6, pn = p & 63;
        vb[i][0] = V[(size_t)(2 * pk2 + 0) * DK + pn];
        vb[i][1] = V[(size_t)(2 * pk2 + 1) * DK + pn];
    }

    {
        uint32_t h[4], l[4];
        split_pack(ra0.x, ra0.y, h[0], l[0]);
        split_pack(ra0.z, ra0.w, h[1], l[1]);
        split_pack(ra1.x, ra1.y, h[2], l[2]);
        split_pack(ra1.z, ra1.w, h[3], l[3]);
        #pragma unroll
        for (int i = 0; i < 4; i++) {
            int j = i ^ sel;
            AsP[0][k2b + j][lrow] = make_uint2(h[j], l[j]);
        }
        #pragma unroll
        for (int i = 0; i < 2; i++) {
            int p = t + 256 * i;
            int pk2 = p >> 6, pn = p & 63;
            uint32_t hh, ll;
            split_pack(vb[i][0], vb[i][1], hh, ll);
            BsP[0][pk2][pn] = make_uint2(hh, ll);
        }
    }
    __syncthreads();

    const int warp = t >> 5, lane = t & 31;
    const int wm = (warp >> 1) * 32;
    const int wn = (warp & 1) * 32;
    const int qrow = lane >> 2, qk = lane & 3;

    float c[2][4][4] = {};

    constexpr int NITER = SEQ / 16;            // 128
    for (int it = 0; it < NITER; ++it) {
        const int buf = it & 1;
        if (it + 1 < NITER) {
            const int k0 = (it + 1) * 16;
            const float* qa = pA + k0;
            ra0 = *(const float4*)(qa); ra1 = *(const float4*)(qa + 4);
            #pragma unroll
            for (int i = 0; i < 2; i++) {
                int p = t + 256 * i;
                int pk2 = p >> 6, pn = p & 63;
                vb[i][0] = V[(size_t)(k0 + 2 * pk2 + 0) * DK + pn];
                vb[i][1] = V[(size_t)(k0 + 2 * pk2 + 1) * DK + pn];
            }
        }

        uint32_t aH[2][4], aL[2][4], bH[4][2], bL[4][2];
        #pragma unroll
        for (int mt = 0; mt < 2; mt++) {
            int m = wm + mt * 16 + qrow;
            uint2 p0 = AsP[buf][qk][m];
            uint2 p1 = AsP[buf][qk][m + 8];
            uint2 p2 = AsP[buf][qk + 4][m];
            uint2 p3 = AsP[buf][qk + 4][m + 8];
            aH[mt][0] = p0.x; aH[mt][1] = p1.x; aH[mt][2] = p2.x; aH[mt][3] = p3.x;
            aL[mt][0] = p0.y; aL[mt][1] = p1.y; aL[mt][2] = p2.y; aL[mt][3] = p3.y;
        }
        #pragma unroll
        for (int nt = 0; nt < 4; nt++) {
            int n = wn + nt * 8 + qrow;
            uint2 q0 = BsP[buf][qk][n];
            uint2 q1 = BsP[buf][qk + 4][n];
            bH[nt][0] = q0.x; bH[nt][1] = q1.x;
            bL[nt][0] = q0.y; bL[nt][1] = q1.y;
        }
        #pragma unroll
        for (int mt = 0; mt < 2; mt++)
            #pragma unroll
            for (int nt = 0; nt < 4; nt++) {
                mma_bf16(c[mt][nt], aH[mt], bH[nt]);
                mma_bf16(c[mt][nt], aH[mt], bL[nt]);
                mma_bf16(c[mt][nt], aL[mt], bH[nt]);
            }

        if (it + 1 < NITER) {
            const int nb = buf ^ 1;
            uint32_t h[4], l[4];
            split_pack(ra0.x, ra0.y, h[0], l[0]);
            split_pack(ra0.z, ra0.w, h[1], l[1]);
            split_pack(ra1.x, ra1.y, h[2], l[2]);
            split_pack(ra1.z, ra1.w, h[3], l[3]);
            #pragma unroll
            for (int i = 0; i < 4; i++) {
                int j = i ^ sel;
                AsP[nb][k2b + j][lrow] = make_uint2(h[j], l[j]);
            }
            #pragma unroll
            for (int i = 0; i < 2; i++) {
                int p = t + 256 * i;
                int pk2 = p >> 6, pn = p & 63;
                uint32_t hh, ll;
                split_pack(vb[i][0], vb[i][1], hh, ll);
                BsP[nb][pk2][pn] = make_uint2(hh, ll);
            }
        }
        __syncthreads();
    }

    const int b = z >> 4, h = z & 15;
    #pragma unroll
    for (int mt = 0; mt < 2; mt++) {
        #pragma unroll
        for (int nt = 0; nt < 4; nt++) {
            int s0 = m0 + wm + mt * 16 + qrow;
            int d  = wn + nt * 8 + qk * 2;
            #pragma unroll
            for (int half = 0; half < 2; half++) {
                int s = s0 + half * 8;
                float2 w = {c[mt][nt][half * 2 + 0], c[mt][nt][half * 2 + 1]};
                *(float2*)(g_ctx + ((size_t)b * SEQ + s) * DM + h * DK + d) = w;
            }
        }
    }
}

// ---------------------------------------------------------------------------
// Row softmax in place. One block (256 thr) per row of 2048. (82.9% HBM)
// ---------------------------------------------------------------------------
__global__ void __launch_bounds__(256)
softmax_kernel(float* __restrict__ attn)
{
    float* p = attn + (size_t)blockIdx.x * SEQ;
    const int t = threadIdx.x;

    float vals[8];
    float mx = -INFINITY;
    #pragma unroll
    for (int c = 0; c < 2; c++) {
        float4 f = *(float4*)(p + c * 1024 + t * 4);
        vals[c * 4 + 0] = f.x; vals[c * 4 + 1] = f.y;
        vals[c * 4 + 2] = f.z; vals[c * 4 + 3] = f.w;
    }
    #pragma unroll
    for (int i = 0; i < 8; i++) mx = fmaxf(mx, vals[i]);

    __shared__ float sm[8];
    #pragma unroll
    for (int o = 16; o; o >>= 1) mx = fmaxf(mx, __shfl_xor_sync(0xffffffffu, mx, o));
    if ((t & 31) == 0) sm[t >> 5] = mx;
    __syncthreads();
    if (t < 32) {
        float v = (t < 8) ? sm[t] : -INFINITY;
        #pragma unroll
        for (int o = 4; o; o >>= 1) v = fmaxf(v, __shfl_xor_sync(0xffffffffu, v, o));
        if (t == 0) sm[0] = v;
    }
    __syncthreads();
    mx = sm[0];

    float s = 0.f;
    #pragma unroll
    for (int i = 0; i < 8; i++) { vals[i] = __expf(vals[i] - mx); s += vals[i]; }

    __shared__ float sm2[8];
    #pragma unroll
    for (int o = 16; o; o >>= 1) s += __shfl_xor_sync(0xffffffffu, s, o);
    if ((t & 31) == 0) sm2[t >> 5] = s;
    __syncthreads();
    if (t < 32) {
        float v = (t < 8) ? sm2[t] : 0.f;
        #pragma unroll
        for (int o = 4; o; o >>= 1) v += __shfl_xor_sync(0xffffffffu, v, o);
        if (t == 0) sm2[0] = v;
    }
    __syncthreads();
    const float inv = 1.0f / sm2[0];

    #pragma unroll
    for (int c = 0; c < 2; c++) {
        float4 f;
        f.x = vals[c * 4 + 0] * inv; f.y = vals[c * 4 + 1] * inv;
        f.z = vals[c * 4 + 2] * inv; f.w = vals[c * 4 + 3] * inv;
        *(float4*)(p + c * 1024 + t * 4) = f;
    }
}

// ---------------------------------------------------------------------------
// Launch. d_out layout: [out: 4096*1024 f32][attn: 32*2048*2048 f32]
// Inputs: x, mask, w_q, w_k, w_v, w_o
// ---------------------------------------------------------------------------
extern "C" void kernel_launch(void* const* d_in, const int* in_sizes, int n_in,
                              void* d_out, int out_size)
{
    const float* x    = (const float*)d_in[0];
    const int*   mask = (const int*)  d_in[1];
    const float* wq   = (const float*)d_in[2];
    const float* wk   = (const float*)d_in[3];
    const float* wv   = (const float*)d_in[4];
    const float* wo   = (const float*)d_in[5];

    float* out  = (float*)d_out;
    float* attn = out + (size_t)MROWS * DM;

    gemm_nt_kernel<0><<<dim3(DM / 128, MROWS / 128, 3), 256>>>(x, wq, wk, wv, nullptr, nullptr);
    gemm_nt_kernel<1><<<dim3(SEQ / 128, SEQ / 128, BH), 256>>>(nullptr, nullptr, nullptr, nullptr, mask, attn);
    softmax_kernel<<<BH * SEQ, 256>>>(attn);
    ctx_kernel<<<dim3(1, SEQ / 128, BH), 256>>>(attn);
    gemm_nt_kernel<2><<<dim3(DM / 128, MROWS / 128, 1), 256>>>(nullptr, wo, nullptr, nullptr, nullptr, out);
}